// round 16
// baseline (speedup 1.0000x reference)
#include <cuda_runtime.h>
#include <cuda_fp16.h>
#include <math.h>

#define HH  16
#define SS  2048
#define DD  1024
#define DHD 64
#define HID 4096

// ---------------- scratch ----------------------------------------------------
__device__ float g_tmp [SS * DD];
__device__ float g_y1  [SS * DD];
__device__ float g_y2  [SS * DD];
__device__ __align__(16) __half g_qh  [HH * SS * DHD];
__device__ __align__(16) __half g_qch [HH * SS * DHD];
__device__ __align__(16) __half g_kch [HH * SS * DHD];
__device__ __align__(16) __half g_yh  [SS * DD];
__device__ __align__(16) __half g_y1h [SS * DD];
__device__ __align__(16) __half g_y2h [SS * DD];
__device__ __align__(16) __half g_ench[SS * DD];
__device__ __align__(16) __half g_wqst[DD * DD];     // [h*64+n][k]
__device__ __align__(16) __half g_wqct[DD * DD];
__device__ __align__(16) __half g_w1t [HID * DD];    // [n][k] transposed
__device__ __align__(16) __half g_w2t [DD * HID];
__device__ __align__(16) __half g_hidh[SS * HID];

// ---------------- helpers ----------------------------------------------------
__device__ __forceinline__ void mma_f16(
    float& d0, float& d1, float& d2, float& d3,
    unsigned a0, unsigned a1, unsigned a2, unsigned a3,
    unsigned b0, unsigned b1)
{
    asm volatile(
        "mma.sync.aligned.m16n8k16.row.col.f32.f16.f16.f32 "
        "{%0,%1,%2,%3}, {%4,%5,%6,%7}, {%8,%9}, {%0,%1,%2,%3};"
        : "+f"(d0), "+f"(d1), "+f"(d2), "+f"(d3)
        : "r"(a0), "r"(a1), "r"(a2), "r"(a3), "r"(b0), "r"(b1));
}
__device__ __forceinline__ void cp16h(__half* dst, const __half* src) {
    unsigned d = (unsigned)__cvta_generic_to_shared(dst);
    asm volatile("cp.async.cg.shared.global [%0], [%1], 16;" :: "r"(d), "l"(src));
}
#define CP_COMMIT() asm volatile("cp.async.commit_group;")
#define CP_WAIT0()  asm volatile("cp.async.wait_group 0;")

__device__ __forceinline__ void ldsm4h(unsigned& r0, unsigned& r1,
                                       unsigned& r2, unsigned& r3, const __half* p)
{
    unsigned a = (unsigned)__cvta_generic_to_shared(p);
    asm volatile("ldmatrix.sync.aligned.m8n8.x4.shared.b16 {%0,%1,%2,%3}, [%4];"
                 : "=r"(r0), "=r"(r1), "=r"(r2), "=r"(r3) : "r"(a));
}
__device__ __forceinline__ void ldsm4t(unsigned& r0, unsigned& r1,
                                       unsigned& r2, unsigned& r3, const __half* p)
{
    unsigned a = (unsigned)__cvta_generic_to_shared(p);
    asm volatile("ldmatrix.sync.aligned.m8n8.x4.trans.shared.b16 {%0,%1,%2,%3}, [%4];"
                 : "=r"(r0), "=r"(r1), "=r"(r2), "=r"(r3) : "r"(a));
}
__device__ __forceinline__ unsigned h2u(float a, float b) {
    __half2 h = __floats2half2_rn(a, b);
    return *(unsigned*)&h;
}
__device__ __forceinline__ float ex2(float x) {
    float y; asm("ex2.approx.ftz.f32 %0, %1;" : "=f"(y) : "f"(x)); return y;
}

// ---------------- conversion kernels -----------------------------------------
__global__ __launch_bounds__(256)
void f2h2_kernel(const float* __restrict__ in0, __half* __restrict__ out0, int n4a,
                 const float* __restrict__ in1, __half* __restrict__ out1, int n4b)
{
    for (int i = blockIdx.x * 256 + threadIdx.x; i < n4a + n4b; i += gridDim.x * 256) {
        const float* in = (i < n4a) ? in0 : in1;
        __half* out = (i < n4a) ? out0 : out1;
        const int j = (i < n4a) ? i : i - n4a;
        float4 v = ((const float4*)in)[j];
        ((__half2*)out)[2 * j]     = __floats2half2_rn(v.x, v.y);
        ((__half2*)out)[2 * j + 1] = __floats2half2_rn(v.z, v.w);
    }
}

__global__ void conv_trans_kernel(const float* __restrict__ in0, __half* __restrict__ out0,
                                  const float* __restrict__ in1, __half* __restrict__ out1,
                                  int R, int C, int zsplit)
{
    __shared__ float t[32][33];
    int z = blockIdx.z;
    const float* in = in0; __half* out = out0;
    if (in1 && z >= zsplit) { in = in1; out = out1; z -= zsplit; }
    const long long bo = (long long)z * R * C;
    in += bo; out += bo;
    const int c0 = blockIdx.x * 32, r0 = blockIdx.y * 32;
    const int tx = threadIdx.x, ty = threadIdx.y;
#pragma unroll
    for (int i = 0; i < 4; i++)
        t[ty + 8 * i][tx] = in[(long long)(r0 + ty + 8 * i) * C + c0 + tx];
    __syncthreads();
#pragma unroll
    for (int i = 0; i < 4; i++)
        out[(long long)(c0 + ty + 8 * i) * R + r0 + tx] = __float2half(t[tx][ty + 8 * i]);
}

// ======================= fp16 tensor-core GEMM (BK=64, 2-stage) =============
// A [M][K] half, B [N][K] half (n-major). 2 CTAs/SM via launch bounds.
#define BM 128
#define BK 64
#define SAH 72

template<int BN>
__global__ __launch_bounds__(256, 2)
void gemm_h(const __half* __restrict__ A, const __half* __restrict__ B,
            const float* __restrict__ bias, float* __restrict__ C,
            __half* __restrict__ Ch,
            const __half* __restrict__ A2, __half* __restrict__ Ch2, int zsplit,
            int K, int lda, int ldb, int ldc,
            int headSplit, int relu)
{
    constexpr int NTT  = BN / 16;
    constexpr int ABUF = BM * SAH;
    constexpr int BBUF = BN * SAH;

    extern __shared__ __half smh[];
    __half* As = smh;               // 2 * ABUF
    __half* Bs = smh + 2 * ABUF;    // 2 * BBUF

    if (A2 && (int)blockIdx.z >= zsplit) { A = A2; Ch = Ch2; }

    const int rowStart = blockIdx.y * BM;
    const int colStart = blockIdx.x * BN;
    const int nK = K / BK;

    const int tid  = threadIdx.x;
    const int wid  = tid >> 5, lane = tid & 31;
    const int g    = lane >> 2, tig = lane & 3;
    const int warpM = wid & 3, warpN = wid >> 2;

    const int a_r = tid >> 3, a_c = (tid & 7) << 3;
    const __half* Agp = A + (long long)(rowStart + a_r) * lda + a_c;
    const __half* Bgp = B + (long long)(colStart + a_r) * ldb + a_c;

    const int am_row = lane & 15;
    const int am_col = (lane & 16) ? 8 : 0;
    const int bn_row = (lane & 7) + ((lane & 16) ? 8 : 0);
    const int bn_col = lane & 8;

    auto issue = [&](int kt) {
        const int k0 = kt * BK;
        __half* Ad = As + (kt & 1) * ABUF;
        __half* Bd = Bs + (kt & 1) * BBUF;
#pragma unroll
        for (int i = 0; i < 4; i++)
            cp16h(Ad + (a_r + 32 * i) * SAH + a_c, Agp + (long long)(32 * i) * lda + k0);
#pragma unroll
        for (int i = 0; i < BN / 32; i++)
            cp16h(Bd + (a_r + 32 * i) * SAH + a_c, Bgp + (long long)(32 * i) * ldb + k0);
        CP_COMMIT();
    };

    float acc[2][NTT][4];
#pragma unroll
    for (int mt = 0; mt < 2; mt++)
#pragma unroll
        for (int nt = 0; nt < NTT; nt++)
#pragma unroll
            for (int i = 0; i < 4; i++) acc[mt][nt][i] = 0.f;

    issue(0);

    for (int kt = 0; kt < nK; kt++) {
        CP_WAIT0();
        __syncthreads();                 // tile kt visible; prev compute done
        if (kt + 1 < nK) issue(kt + 1);

        const __half* Ac = As + (kt & 1) * ABUF;
        const __half* Bc = Bs + (kt & 1) * BBUF;
#pragma unroll
        for (int ks = 0; ks < 4; ks++) {
            const int ko = ks * 16;
            unsigned af[2][4];
#pragma unroll
            for (int mt = 0; mt < 2; mt++)
                ldsm4h(af[mt][0], af[mt][1], af[mt][2], af[mt][3],
                       Ac + (warpM * 32 + mt * 16 + am_row) * SAH + ko + am_col);
            unsigned bf[NTT][2];
#pragma unroll
            for (int np = 0; np < NTT / 2; np++) {
                const int nb = warpN * (BN / 2) + np * 16;
                unsigned r0, r1, r2, r3;
                ldsm4h(r0, r1, r2, r3, Bc + (nb + bn_row) * SAH + ko + bn_col);
                bf[2 * np][0] = r0;     bf[2 * np][1] = r1;
                bf[2 * np + 1][0] = r2; bf[2 * np + 1][1] = r3;
            }
#pragma unroll
            for (int mt = 0; mt < 2; mt++)
#pragma unroll
                for (int nt = 0; nt < NTT; nt++)
                    mma_f16(acc[mt][nt][0], acc[mt][nt][1], acc[mt][nt][2], acc[mt][nt][3],
                            af[mt][0], af[mt][1], af[mt][2], af[mt][3],
                            bf[nt][0], bf[nt][1]);
        }
        __syncthreads();                 // compute done before buffer reuse
    }

#pragma unroll
    for (int mt = 0; mt < 2; mt++) {
        const int r = rowStart + warpM * 32 + mt * 16 + g;
#pragma unroll
        for (int nt = 0; nt < NTT; nt++) {
            const int cc = colStart + warpN * (BN / 2) + nt * 8 + 2 * tig;
            const float bb0 = bias ? bias[cc]     : 0.f;
            const float bb1 = bias ? bias[cc + 1] : 0.f;
            float v0 = acc[mt][nt][0] + bb0;
            float v1 = acc[mt][nt][1] + bb1;
            float v2 = acc[mt][nt][2] + bb0;
            float v3 = acc[mt][nt][3] + bb1;
            if (relu) { v0 = fmaxf(v0, 0.f); v1 = fmaxf(v1, 0.f);
                        v2 = fmaxf(v2, 0.f); v3 = fmaxf(v3, 0.f); }
            if (headSplit) {
                const long long ro =
                    ((long long)(cc >> 6) * SS + r) * DHD + (cc & 63);
                *(__half2*)&Ch[ro]           = __floats2half2_rn(v0, v1);
                *(__half2*)&Ch[ro + 8 * DHD] = __floats2half2_rn(v2, v3);
            } else if (Ch) {
                *(__half2*)&Ch[(long long)r       * ldc + cc] = __floats2half2_rn(v0, v1);
                *(__half2*)&Ch[(long long)(r + 8) * ldc + cc] = __floats2half2_rn(v2, v3);
            } else {
                *(float2*)&C[(long long)r       * ldc + cc] = make_float2(v0, v1);
                *(float2*)&C[(long long)(r + 8) * ldc + cc] = make_float2(v2, v3);
            }
        }
    }
}

// ======================= fp16 flash attention (round-13) ====================
#define KST 72
#define SM_SCALE2 0.18033688f

template<bool CAUSAL>
__global__ __launch_bounds__(256)
void flash_h(const __half* __restrict__ Q, const __half* __restrict__ KV,
             float* __restrict__ O)
{
    extern __shared__ __half smh[];
    __half* Ks = smh;
    __half* Qs = smh + 2 * 64 * KST;

    const int h = blockIdx.y;
    const int rowBlk = CAUSAL ? (gridDim.x - 1 - blockIdx.x) : blockIdx.x;
    const __half* Qh = Q  + (long long)h * SS * DHD + (long long)rowBlk * 128 * DHD;
    const __half* Kh = KV + (long long)h * SS * DHD;

    const int tid = threadIdx.x, wid = tid >> 5, lane = tid & 31;
    const int g = lane >> 2, tig = lane & 3;
    const int mr = wid * 16;

    const int am_row = lane & 15;
    const int am_col = (lane & 16) ? 8 : 0;
    const int bn_row = (lane & 7) + ((lane & 16) ? 8 : 0);
    const int bn_col = lane & 8;
    const int tv_row = (lane & 7) + (lane & 8);
    const int tv_col = (lane & 16) ? 8 : 0;

    const int k_r = tid >> 3, k_c = (tid & 7) << 3;

    auto issueK = [&](int t) {
        __half* Kd = Ks + (t & 1) * 64 * KST;
        const __half* src = Kh + (long long)(t * 64 + k_r) * DHD + k_c;
        cp16h(Kd + k_r * KST + k_c, src);
        cp16h(Kd + (k_r + 32) * KST + k_c, src + 32 * DHD);
        CP_COMMIT();
    };

    for (int i = tid; i < 128 * 8; i += 256) {
        const int r = i >> 3, c8 = (i & 7) << 3;
        *(uint4*)&Qs[r * KST + c8] = *(const uint4*)(Qh + (long long)r * DHD + c8);
    }
    issueK(0);
    __syncthreads();
    unsigned qf[4][4];
#pragma unroll
    for (int ks = 0; ks < 4; ks++)
        ldsm4h(qf[ks][0], qf[ks][1], qf[ks][2], qf[ks][3],
               Qs + (mr + am_row) * KST + ks * 16 + am_col);

    float o[8][4];
#pragma unroll
    for (int nt = 0; nt < 8; nt++)
#pragma unroll
        for (int i = 0; i < 4; i++) o[nt][i] = 0.f;
    float m0 = -1e30f, m1 = -1e30f, l0 = 0.f, l1 = 0.f;

    const int nTiles = CAUSAL ? 2 * (rowBlk + 1) : SS / 64;
    const int r0 = rowBlk * 128 + mr + g;
    const int r1 = r0 + 8;

    auto tile_body = [&](int t, bool MASKED) {
        CP_WAIT0();
        __syncthreads();
        if (t + 1 < nTiles) issueK(t + 1);
        const __half* Kc = Ks + (t & 1) * 64 * KST;

        float s[8][4];
#pragma unroll
        for (int nt = 0; nt < 8; nt++) { s[nt][0] = s[nt][1] = s[nt][2] = s[nt][3] = 0.f; }
#pragma unroll
        for (int ks = 0; ks < 4; ks++) {
#pragma unroll
            for (int tp = 0; tp < 4; tp++) {
                unsigned b0, b1, b2, b3;
                ldsm4h(b0, b1, b2, b3,
                       Kc + (tp * 16 + bn_row) * KST + ks * 16 + bn_col);
                mma_f16(s[2*tp][0], s[2*tp][1], s[2*tp][2], s[2*tp][3],
                        qf[ks][0], qf[ks][1], qf[ks][2], qf[ks][3], b0, b1);
                mma_f16(s[2*tp+1][0], s[2*tp+1][1], s[2*tp+1][2], s[2*tp+1][3],
                        qf[ks][0], qf[ks][1], qf[ks][2], qf[ks][3], b2, b3);
            }
        }

        const int cb = t * 64;
        float tm0 = -1e30f, tm1 = -1e30f;
#pragma unroll
        for (int nt = 0; nt < 8; nt++) {
            s[nt][0] *= SM_SCALE2; s[nt][1] *= SM_SCALE2;
            s[nt][2] *= SM_SCALE2; s[nt][3] *= SM_SCALE2;
            if (MASKED) {
                const int c0 = cb + nt * 8 + 2 * tig, c1 = c0 + 1;
                if (c0 > r0) s[nt][0] = -1e30f;
                if (c1 > r0) s[nt][1] = -1e30f;
                if (c0 > r1) s[nt][2] = -1e30f;
                if (c1 > r1) s[nt][3] = -1e30f;
            }
            tm0 = fmaxf(tm0, fmaxf(s[nt][0], s[nt][1]));
            tm1 = fmaxf(tm1, fmaxf(s[nt][2], s[nt][3]));
        }
        tm0 = fmaxf(tm0, __shfl_xor_sync(0xffffffffu, tm0, 1));
        tm0 = fmaxf(tm0, __shfl_xor_sync(0xffffffffu, tm0, 2));
        tm1 = fmaxf(tm1, __shfl_xor_sync(0xffffffffu, tm1, 1));
        tm1 = fmaxf(tm1, __shfl_xor_sync(0xffffffffu, tm1, 2));

        const float mn0 = fmaxf(m0, tm0), mn1 = fmaxf(m1, tm1);
        const float corr0 = ex2(m0 - mn0), corr1 = ex2(m1 - mn1);
        m0 = mn0; m1 = mn1;

        float rs0 = 0.f, rs1 = 0.f;
        unsigned pf[4][4];
#pragma unroll
        for (int tp = 0; tp < 4; tp++) {
            float* e0 = s[2 * tp];
            float* e1 = s[2 * tp + 1];
            e0[0] = ex2(e0[0] - mn0); e0[1] = ex2(e0[1] - mn0);
            e0[2] = ex2(e0[2] - mn1); e0[3] = ex2(e0[3] - mn1);
            e1[0] = ex2(e1[0] - mn0); e1[1] = ex2(e1[1] - mn0);
            e1[2] = ex2(e1[2] - mn1); e1[3] = ex2(e1[3] - mn1);
            rs0 += e0[0] + e0[1] + e1[0] + e1[1];
            rs1 += e0[2] + e0[3] + e1[2] + e1[3];
            pf[tp][0] = h2u(e0[0], e0[1]);
            pf[tp][1] = h2u(e0[2], e0[3]);
            pf[tp][2] = h2u(e1[0], e1[1]);
            pf[tp][3] = h2u(e1[2], e1[3]);
        }
        rs0 += __shfl_xor_sync(0xffffffffu, rs0, 1);
        rs0 += __shfl_xor_sync(0xffffffffu, rs0, 2);
        rs1 += __shfl_xor_sync(0xffffffffu, rs1, 1);
        rs1 += __shfl_xor_sync(0xffffffffu, rs1, 2);
        l0 = l0 * corr0 + rs0;
        l1 = l1 * corr1 + rs1;
#pragma unroll
        for (int nt = 0; nt < 8; nt++) {
            o[nt][0] *= corr0; o[nt][1] *= corr0;
            o[nt][2] *= corr1; o[nt][3] *= corr1;
        }

#pragma unroll
        for (int ts = 0; ts < 4; ts++) {
#pragma unroll
            for (int ep = 0; ep < 4; ep++) {
                unsigned b0, b1, b2, b3;
                ldsm4t(b0, b1, b2, b3,
                       Kc + (ts * 16 + tv_row) * KST + ep * 16 + tv_col);
                mma_f16(o[2*ep][0], o[2*ep][1], o[2*ep][2], o[2*ep][3],
                        pf[ts][0], pf[ts][1], pf[ts][2], pf[ts][3], b0, b1);
                mma_f16(o[2*ep+1][0], o[2*ep+1][1], o[2*ep+1][2], o[2*ep+1][3],
                        pf[ts][0], pf[ts][1], pf[ts][2], pf[ts][3], b2, b3);
            }
        }
    };

    if (CAUSAL) {
        for (int t = 0; t < nTiles - 2; t++) tile_body(t, false);
        tile_body(nTiles - 2, true);
        tile_body(nTiles - 1, true);
    } else {
        for (int t = 0; t < nTiles; t++) tile_body(t, false);
    }

    const float inv0 = 1.f / l0, inv1 = 1.f / l1;
    float* Oh = O + (long long)(rowBlk * 128) * DD + h * DHD;
#pragma unroll
    for (int nt = 0; nt < 8; nt++) {
        const int c = nt * 8 + 2 * tig;
        *(float2*)&Oh[(long long)(mr + g)     * DD + c] =
            make_float2(o[nt][0] * inv0, o[nt][1] * inv0);
        *(float2*)&Oh[(long long)(mr + g + 8) * DD + c] =
            make_float2(o[nt][2] * inv1, o[nt][3] * inv1);
    }
}

// ---------------- add + LayerNorm (float4) -----------------------------------
__global__ __launch_bounds__(256)
void add_ln_kernel(const float* __restrict__ a, const float* __restrict__ b,
                   const float* __restrict__ gamma, const float* __restrict__ beta,
                   float* __restrict__ out, __half* __restrict__ hout)
{
    const int row = blockIdx.x;
    const int tid = threadIdx.x;
    const float4* pa = (const float4*)(a + (long long)row * DD);
    const float4* pb = (const float4*)(b + (long long)row * DD);
    __shared__ float red[256];

    float4 v = pa[tid], w = pb[tid];
    v.x += w.x; v.y += w.y; v.z += w.z; v.w += w.w;
    red[tid] = v.x + v.y + v.z + v.w; __syncthreads();
    for (int o = 128; o; o >>= 1) { if (tid < o) red[tid] += red[tid + o]; __syncthreads(); }
    const float mu = red[0] * (1.f / DD); __syncthreads();

    float var = (v.x - mu) * (v.x - mu) + (v.y - mu) * (v.y - mu)
              + (v.z - mu) * (v.z - mu) + (v.w - mu) * (v.w - mu);
    red[tid] = var; __syncthreads();
    for (int o = 128; o; o >>= 1) { if (tid < o) red[tid] += red[tid + o]; __syncthreads(); }
    const float rs = rsqrtf(red[0] * (1.f / DD) + 1e-5f); __syncthreads();

    const float4 gm = ((const float4*)gamma)[tid];
    const float4 bt = ((const float4*)beta)[tid];
    float4 ov;
    ov.x = (v.x - mu) * rs * gm.x + bt.x;
    ov.y = (v.y - mu) * rs * gm.y + bt.y;
    ov.z = (v.z - mu) * rs * gm.z + bt.z;
    ov.w = (v.w - mu) * rs * gm.w + bt.w;
    if (out) ((float4*)(out + (long long)row * DD))[tid] = ov;
    if (hout) {
        __half2* hp = (__half2*)(hout + (long long)row * DD);
        hp[2 * tid]     = __floats2half2_rn(ov.x, ov.y);
        hp[2 * tid + 1] = __floats2half2_rn(ov.z, ov.w);
    }
}

// ---------------- orchestration ----------------------------------------------
extern "C" void kernel_launch(void* const* d_in, const int* in_sizes, int n_in,
                              void* d_out, int out_size)
{
    const float* y    = (const float*)d_in[0];
    const float* enc  = (const float*)d_in[1];
    const float* Wqs  = (const float*)d_in[2];
    const float* bqs  = (const float*)d_in[3];
    const float* Wqc  = (const float*)d_in[4];
    const float* bqc  = (const float*)d_in[5];
    const float* g1   = (const float*)d_in[6];
    const float* be1  = (const float*)d_in[7];
    const float* g2   = (const float*)d_in[8];
    const float* be2  = (const float*)d_in[9];
    const float* g3   = (const float*)d_in[10];
    const float* be3  = (const float*)d_in[11];
    const float* w1   = (const float*)d_in[12];
    const float* b1   = (const float*)d_in[13];
    const float* w2   = (const float*)d_in[14];
    const float* b2   = (const float*)d_in[15];
    float* out = (float*)d_out;

    float *tmp, *y1, *y2;
    __half *qh, *qch, *kch, *yh, *y1h, *y2h, *ench, *wqst, *wqct, *w1t, *w2t, *hidh;
    cudaGetSymbolAddress((void**)&tmp,  g_tmp);
    cudaGetSymbolAddress((void**)&y1,   g_y1);
    cudaGetSymbolAddress((void**)&y2,   g_y2);
    cudaGetSymbolAddress((void**)&qh,   g_qh);
    cudaGetSymbolAddress((void**)&qch,  g_qch);
    cudaGetSymbolAddress((void**)&kch,  g_kch);
    cudaGetSymbolAddress((void**)&yh,   g_yh);
    cudaGetSymbolAddress((void**)&y1h,  g_y1h);
    cudaGetSymbolAddress((void**)&y2h,  g_y2h);
    cudaGetSymbolAddress((void**)&ench, g_ench);
    cudaGetSymbolAddress((void**)&wqst, g_wqst);
    cudaGetSymbolAddress((void**)&wqct, g_wqct);
    cudaGetSymbolAddress((void**)&w1t,  g_w1t);
    cudaGetSymbolAddress((void**)&w2t,  g_w2t);
    cudaGetSymbolAddress((void**)&hidh, g_hidh);

    const int GS64  = 2 * (BM + 64)  * SAH * 2;   // 55296
    const int GS128 = 2 * (BM + 128) * SAH * 2;   // 73728
    const int FSMEM = (2 * 64 + 128) * KST * 2;   // 36864

    const void* fg64   = (const void*)&gemm_h<64>;
    const void* fg128  = (const void*)&gemm_h<128>;
    const void* ffc    = (const void*)&flash_h<true>;
    const void* ffn    = (const void*)&flash_h<false>;
    cudaFuncSetAttribute(fg64,  cudaFuncAttributeMaxDynamicSharedMemorySize, GS64);
    cudaFuncSetAttribute(fg128, cudaFuncAttributeMaxDynamicSharedMemorySize, GS128);
    cudaFuncSetAttribute(ffc,   cudaFuncAttributeMaxDynamicSharedMemorySize, FSMEM);
    cudaFuncSetAttribute(ffn,   cudaFuncAttributeMaxDynamicSharedMemorySize, FSMEM);

    // ---- conversions ----
    f2h2_kernel<<<592, 256>>>(y, yh, SS * DD / 4, enc, ench, SS * DD / 4);
    conv_trans_kernel<<<dim3(DHD / 32, DD / 32, 2 * HH), dim3(32, 8)>>>(
        Wqs, wqst, Wqc, wqct, DD, DHD, HH);
    conv_trans_kernel<<<dim3(HID / 32, DD / 32, 1), dim3(32, 8)>>>(
        w1, w1t, nullptr, nullptr, DD, HID, 1);
    conv_trans_kernel<<<dim3(DD / 32, HID / 32, 1), dim3(32, 8)>>>(
        w2, w2t, nullptr, nullptr, HID, DD, 1);

    // ---- self attention (q = k = v): full-width GEMM, per-head output ----
    gemm_h<128><<<dim3(DD / 128, SS / BM, 1), 256, GS128>>>(
        yh, wqst, bqs, nullptr, qh, nullptr, nullptr, 0,
        DD, DD, DD, DD, 1, 0);
    flash_h<true><<<dim3(SS / 128, HH), 256, FSMEM>>>(qh, qh, tmp);
    add_ln_kernel<<<SS, 256>>>(y, tmp, g1, be1, y1, y1h);

    // ---- cross attention: fused q+k full-width, per-head output ----
    gemm_h<128><<<dim3(DD / 128, SS / BM, 2), 256, GS128>>>(
        y1h, wqct, bqc, nullptr, qch, ench, kch, 1,
        DD, DD, DD, DD, 1, 0);
    flash_h<false><<<dim3(SS / 128, HH), 256, FSMEM>>>(qch, kch, tmp);
    add_ln_kernel<<<SS, 256>>>(y1, tmp, g2, be2, y2, y2h);

    // ---- FFN ----
    gemm_h<128><<<dim3(HID / 128, SS / BM, 1), 256, GS128>>>(
        y2h, w1t, b1, nullptr, hidh, nullptr, nullptr, 0,
        DD, DD, DD, HID, 0, 1);
    gemm_h<64><<<dim3(DD / 64, SS / BM, 1), 256, GS64>>>(
        hidh, w2t, b2, tmp, nullptr, nullptr, nullptr, 0,
        HID, HID, HID, DD, 0, 0);
    add_ln_kernel<<<SS, 256>>>(y2, tmp, g3, be3, out, nullptr);
}

// round 17
// speedup vs baseline: 1.0015x; 1.0015x over previous
#include <cuda_runtime.h>
#include <cuda_fp16.h>
#include <math.h>

#define HH  16
#define SS  2048
#define DD  1024
#define DHD 64
#define HID 4096

// ---------------- scratch ----------------------------------------------------
__device__ float g_tmp [SS * DD];
__device__ float g_y1  [SS * DD];
__device__ float g_y2  [SS * DD];
__device__ __align__(16) __half g_qh  [HH * SS * DHD];
__device__ __align__(16) __half g_qch [HH * SS * DHD];
__device__ __align__(16) __half g_kch [HH * SS * DHD];
__device__ __align__(16) __half g_yh  [SS * DD];
__device__ __align__(16) __half g_y1h [SS * DD];
__device__ __align__(16) __half g_y2h [SS * DD];
__device__ __align__(16) __half g_ench[SS * DD];
__device__ __align__(16) __half g_wqst[DD * DD];
__device__ __align__(16) __half g_wqct[DD * DD];
__device__ __align__(16) __half g_w1t [HID * DD];
__device__ __align__(16) __half g_w2t [DD * HID];
__device__ __align__(16) __half g_hidh[SS * HID];

// ---------------- helpers ----------------------------------------------------
__device__ __forceinline__ void mma_f16(
    float& d0, float& d1, float& d2, float& d3,
    unsigned a0, unsigned a1, unsigned a2, unsigned a3,
    unsigned b0, unsigned b1)
{
    asm volatile(
        "mma.sync.aligned.m16n8k16.row.col.f32.f16.f16.f32 "
        "{%0,%1,%2,%3}, {%4,%5,%6,%7}, {%8,%9}, {%0,%1,%2,%3};"
        : "+f"(d0), "+f"(d1), "+f"(d2), "+f"(d3)
        : "r"(a0), "r"(a1), "r"(a2), "r"(a3), "r"(b0), "r"(b1));
}
__device__ __forceinline__ void cp16h(__half* dst, const __half* src) {
    unsigned d = (unsigned)__cvta_generic_to_shared(dst);
    asm volatile("cp.async.cg.shared.global [%0], [%1], 16;" :: "r"(d), "l"(src));
}
#define CP_COMMIT() asm volatile("cp.async.commit_group;")
#define CP_WAIT0()  asm volatile("cp.async.wait_group 0;")

__device__ __forceinline__ void ldsm4h(unsigned& r0, unsigned& r1,
                                       unsigned& r2, unsigned& r3, const __half* p)
{
    unsigned a = (unsigned)__cvta_generic_to_shared(p);
    asm volatile("ldmatrix.sync.aligned.m8n8.x4.shared.b16 {%0,%1,%2,%3}, [%4];"
                 : "=r"(r0), "=r"(r1), "=r"(r2), "=r"(r3) : "r"(a));
}
__device__ __forceinline__ void ldsm4t(unsigned& r0, unsigned& r1,
                                       unsigned& r2, unsigned& r3, const __half* p)
{
    unsigned a = (unsigned)__cvta_generic_to_shared(p);
    asm volatile("ldmatrix.sync.aligned.m8n8.x4.trans.shared.b16 {%0,%1,%2,%3}, [%4];"
                 : "=r"(r0), "=r"(r1), "=r"(r2), "=r"(r3) : "r"(a));
}
__device__ __forceinline__ unsigned h2u(float a, float b) {
    __half2 h = __floats2half2_rn(a, b);
    return *(unsigned*)&h;
}
__device__ __forceinline__ float ex2(float x) {
    float y; asm("ex2.approx.ftz.f32 %0, %1;" : "=f"(y) : "f"(x)); return y;
}

// ---------------- conversion kernels -----------------------------------------
__global__ __launch_bounds__(256)
void f2h2_kernel(const float* __restrict__ in0, __half* __restrict__ out0, int n4a,
                 const float* __restrict__ in1, __half* __restrict__ out1, int n4b)
{
    for (int i = blockIdx.x * 256 + threadIdx.x; i < n4a + n4b; i += gridDim.x * 256) {
        const float* in = (i < n4a) ? in0 : in1;
        __half* out = (i < n4a) ? out0 : out1;
        const int j = (i < n4a) ? i : i - n4a;
        float4 v = ((const float4*)in)[j];
        ((__half2*)out)[2 * j]     = __floats2half2_rn(v.x, v.y);
        ((__half2*)out)[2 * j + 1] = __floats2half2_rn(v.z, v.w);
    }
}

__global__ void conv_trans_kernel(const float* __restrict__ in0, __half* __restrict__ out0,
                                  const float* __restrict__ in1, __half* __restrict__ out1,
                                  int R, int C, int zsplit)
{
    __shared__ float t[32][33];
    int z = blockIdx.z;
    const float* in = in0; __half* out = out0;
    if (in1 && z >= zsplit) { in = in1; out = out1; z -= zsplit; }
    const long long bo = (long long)z * R * C;
    in += bo; out += bo;
    const int c0 = blockIdx.x * 32, r0 = blockIdx.y * 32;
    const int tx = threadIdx.x, ty = threadIdx.y;
#pragma unroll
    for (int i = 0; i < 4; i++)
        t[ty + 8 * i][tx] = in[(long long)(r0 + ty + 8 * i) * C + c0 + tx];
    __syncthreads();
#pragma unroll
    for (int i = 0; i < 4; i++)
        out[(long long)(c0 + ty + 8 * i) * R + r0 + tx] = __float2half(t[tx][ty + 8 * i]);
}

// ======================= fp16 tensor-core GEMM (BK=64, 2-stage) =============
#define BM 128
#define BK 64
#define SAH 72

template<int BN>
__global__ __launch_bounds__(256, 2)
void gemm_h(const __half* __restrict__ A, const __half* __restrict__ B,
            const float* __restrict__ bias, float* __restrict__ C,
            __half* __restrict__ Ch,
            const __half* __restrict__ A2, __half* __restrict__ Ch2, int zsplit,
            int K, int lda, int ldb, int ldc,
            int headSplit, int relu)
{
    constexpr int NTT  = BN / 16;
    constexpr int ABUF = BM * SAH;
    constexpr int BBUF = BN * SAH;

    extern __shared__ __half smh[];
    __half* As = smh;
    __half* Bs = smh + 2 * ABUF;

    if (A2 && (int)blockIdx.z >= zsplit) { A = A2; Ch = Ch2; }

    const int rowStart = blockIdx.y * BM;
    const int colStart = blockIdx.x * BN;
    const int nK = K / BK;

    const int tid  = threadIdx.x;
    const int wid  = tid >> 5, lane = tid & 31;
    const int g    = lane >> 2, tig = lane & 3;
    const int warpM = wid & 3, warpN = wid >> 2;

    const int a_r = tid >> 3, a_c = (tid & 7) << 3;
    const __half* Agp = A + (long long)(rowStart + a_r) * lda + a_c;
    const __half* Bgp = B + (long long)(colStart + a_r) * ldb + a_c;

    const int am_row = lane & 15;
    const int am_col = (lane & 16) ? 8 : 0;
    const int bn_row = (lane & 7) + ((lane & 16) ? 8 : 0);
    const int bn_col = lane & 8;

    auto issue = [&](int kt) {
        const int k0 = kt * BK;
        __half* Ad = As + (kt & 1) * ABUF;
        __half* Bd = Bs + (kt & 1) * BBUF;
#pragma unroll
        for (int i = 0; i < 4; i++)
            cp16h(Ad + (a_r + 32 * i) * SAH + a_c, Agp + (long long)(32 * i) * lda + k0);
#pragma unroll
        for (int i = 0; i < BN / 32; i++)
            cp16h(Bd + (a_r + 32 * i) * SAH + a_c, Bgp + (long long)(32 * i) * ldb + k0);
        CP_COMMIT();
    };

    float acc[2][NTT][4];
#pragma unroll
    for (int mt = 0; mt < 2; mt++)
#pragma unroll
        for (int nt = 0; nt < NTT; nt++)
#pragma unroll
            for (int i = 0; i < 4; i++) acc[mt][nt][i] = 0.f;

    issue(0);

    for (int kt = 0; kt < nK; kt++) {
        CP_WAIT0();
        __syncthreads();
        if (kt + 1 < nK) issue(kt + 1);

        const __half* Ac = As + (kt & 1) * ABUF;
        const __half* Bc = Bs + (kt & 1) * BBUF;
#pragma unroll
        for (int ks = 0; ks < 4; ks++) {
            const int ko = ks * 16;
            unsigned af[2][4];
#pragma unroll
            for (int mt = 0; mt < 2; mt++)
                ldsm4h(af[mt][0], af[mt][1], af[mt][2], af[mt][3],
                       Ac + (warpM * 32 + mt * 16 + am_row) * SAH + ko + am_col);
            unsigned bf[NTT][2];
#pragma unroll
            for (int np = 0; np < NTT / 2; np++) {
                const int nb = warpN * (BN / 2) + np * 16;
                unsigned r0, r1, r2, r3;
                ldsm4h(r0, r1, r2, r3, Bc + (nb + bn_row) * SAH + ko + bn_col);
                bf[2 * np][0] = r0;     bf[2 * np][1] = r1;
                bf[2 * np + 1][0] = r2; bf[2 * np + 1][1] = r3;
            }
#pragma unroll
            for (int mt = 0; mt < 2; mt++)
#pragma unroll
                for (int nt = 0; nt < NTT; nt++)
                    mma_f16(acc[mt][nt][0], acc[mt][nt][1], acc[mt][nt][2], acc[mt][nt][3],
                            af[mt][0], af[mt][1], af[mt][2], af[mt][3],
                            bf[nt][0], bf[nt][1]);
        }
        __syncthreads();
    }

#pragma unroll
    for (int mt = 0; mt < 2; mt++) {
        const int r = rowStart + warpM * 32 + mt * 16 + g;
#pragma unroll
        for (int nt = 0; nt < NTT; nt++) {
            const int cc = colStart + warpN * (BN / 2) + nt * 8 + 2 * tig;
            const float bb0 = bias ? bias[cc]     : 0.f;
            const float bb1 = bias ? bias[cc + 1] : 0.f;
            float v0 = acc[mt][nt][0] + bb0;
            float v1 = acc[mt][nt][1] + bb1;
            float v2 = acc[mt][nt][2] + bb0;
            float v3 = acc[mt][nt][3] + bb1;
            if (relu) { v0 = fmaxf(v0, 0.f); v1 = fmaxf(v1, 0.f);
                        v2 = fmaxf(v2, 0.f); v3 = fmaxf(v3, 0.f); }
            if (headSplit) {
                const long long ro =
                    ((long long)(cc >> 6) * SS + r) * DHD + (cc & 63);
                *(__half2*)&Ch[ro]           = __floats2half2_rn(v0, v1);
                *(__half2*)&Ch[ro + 8 * DHD] = __floats2half2_rn(v2, v3);
            } else if (Ch) {
                *(__half2*)&Ch[(long long)r       * ldc + cc] = __floats2half2_rn(v0, v1);
                *(__half2*)&Ch[(long long)(r + 8) * ldc + cc] = __floats2half2_rn(v2, v3);
            } else {
                *(float2*)&C[(long long)r       * ldc + cc] = make_float2(v0, v1);
                *(float2*)&C[(long long)(r + 8) * ldc + cc] = make_float2(v2, v3);
            }
        }
    }
}

// ======================= fp16 flash attention (2 CTAs/SM) ===================
#define KST 72
#define SM_SCALE2 0.18033688f

template<bool CAUSAL>
__global__ __launch_bounds__(256, 2)
void flash_h(const __half* __restrict__ Q, const __half* __restrict__ KV,
             float* __restrict__ O)
{
    extern __shared__ __half smh[];
    __half* Ks = smh;
    __half* Qs = smh + 2 * 64 * KST;

    const int h = blockIdx.y;
    const int rowBlk = CAUSAL ? (gridDim.x - 1 - blockIdx.x) : blockIdx.x;
    const __half* Qh = Q  + (long long)h * SS * DHD + (long long)rowBlk * 128 * DHD;
    const __half* Kh = KV + (long long)h * SS * DHD;

    const int tid = threadIdx.x, wid = tid >> 5, lane = tid & 31;
    const int g = lane >> 2, tig = lane & 3;
    const int mr = wid * 16;

    const int am_row = lane & 15;
    const int am_col = (lane & 16) ? 8 : 0;
    const int bn_row = (lane & 7) + ((lane & 16) ? 8 : 0);
    const int bn_col = lane & 8;
    const int tv_row = (lane & 7) + (lane & 8);
    const int tv_col = (lane & 16) ? 8 : 0;

    const int k_r = tid >> 3, k_c = (tid & 7) << 3;

    auto issueK = [&](int t) {
        __half* Kd = Ks + (t & 1) * 64 * KST;
        const __half* src = Kh + (long long)(t * 64 + k_r) * DHD + k_c;
        cp16h(Kd + k_r * KST + k_c, src);
        cp16h(Kd + (k_r + 32) * KST + k_c, src + 32 * DHD);
        CP_COMMIT();
    };

    for (int i = tid; i < 128 * 8; i += 256) {
        const int r = i >> 3, c8 = (i & 7) << 3;
        *(uint4*)&Qs[r * KST + c8] = *(const uint4*)(Qh + (long long)r * DHD + c8);
    }
    issueK(0);
    __syncthreads();
    unsigned qf[4][4];
#pragma unroll
    for (int ks = 0; ks < 4; ks++)
        ldsm4h(qf[ks][0], qf[ks][1], qf[ks][2], qf[ks][3],
               Qs + (mr + am_row) * KST + ks * 16 + am_col);

    float o[8][4];
#pragma unroll
    for (int nt = 0; nt < 8; nt++)
#pragma unroll
        for (int i = 0; i < 4; i++) o[nt][i] = 0.f;
    float m0 = -1e30f, m1 = -1e30f, l0 = 0.f, l1 = 0.f;

    const int nTiles = CAUSAL ? 2 * (rowBlk + 1) : SS / 64;
    const int r0 = rowBlk * 128 + mr + g;
    const int r1 = r0 + 8;

    auto tile_body = [&](int t, bool MASKED) {
        CP_WAIT0();
        __syncthreads();
        if (t + 1 < nTiles) issueK(t + 1);
        const __half* Kc = Ks + (t & 1) * 64 * KST;

        float s[8][4];
#pragma unroll
        for (int nt = 0; nt < 8; nt++) { s[nt][0] = s[nt][1] = s[nt][2] = s[nt][3] = 0.f; }
#pragma unroll
        for (int ks = 0; ks < 4; ks++) {
#pragma unroll
            for (int tp = 0; tp < 4; tp++) {
                unsigned b0, b1, b2, b3;
                ldsm4h(b0, b1, b2, b3,
                       Kc + (tp * 16 + bn_row) * KST + ks * 16 + bn_col);
                mma_f16(s[2*tp][0], s[2*tp][1], s[2*tp][2], s[2*tp][3],
                        qf[ks][0], qf[ks][1], qf[ks][2], qf[ks][3], b0, b1);
                mma_f16(s[2*tp+1][0], s[2*tp+1][1], s[2*tp+1][2], s[2*tp+1][3],
                        qf[ks][0], qf[ks][1], qf[ks][2], qf[ks][3], b2, b3);
            }
        }

        const int cb = t * 64;
        float tm0 = -1e30f, tm1 = -1e30f;
#pragma unroll
        for (int nt = 0; nt < 8; nt++) {
            s[nt][0] *= SM_SCALE2; s[nt][1] *= SM_SCALE2;
            s[nt][2] *= SM_SCALE2; s[nt][3] *= SM_SCALE2;
            if (MASKED) {
                const int c0 = cb + nt * 8 + 2 * tig, c1 = c0 + 1;
                if (c0 > r0) s[nt][0] = -1e30f;
                if (c1 > r0) s[nt][1] = -1e30f;
                if (c0 > r1) s[nt][2] = -1e30f;
                if (c1 > r1) s[nt][3] = -1e30f;
            }
            tm0 = fmaxf(tm0, fmaxf(s[nt][0], s[nt][1]));
            tm1 = fmaxf(tm1, fmaxf(s[nt][2], s[nt][3]));
        }
        tm0 = fmaxf(tm0, __shfl_xor_sync(0xffffffffu, tm0, 1));
        tm0 = fmaxf(tm0, __shfl_xor_sync(0xffffffffu, tm0, 2));
        tm1 = fmaxf(tm1, __shfl_xor_sync(0xffffffffu, tm1, 1));
        tm1 = fmaxf(tm1, __shfl_xor_sync(0xffffffffu, tm1, 2));

        const float mn0 = fmaxf(m0, tm0), mn1 = fmaxf(m1, tm1);
        const float corr0 = ex2(m0 - mn0), corr1 = ex2(m1 - mn1);
        m0 = mn0; m1 = mn1;

        float rs0 = 0.f, rs1 = 0.f;
        unsigned pf[4][4];
#pragma unroll
        for (int tp = 0; tp < 4; tp++) {
            float* e0 = s[2 * tp];
            float* e1 = s[2 * tp + 1];
            e0[0] = ex2(e0[0] - mn0); e0[1] = ex2(e0[1] - mn0);
            e0[2] = ex2(e0[2] - mn1); e0[3] = ex2(e0[3] - mn1);
            e1[0] = ex2(e1[0] - mn0); e1[1] = ex2(e1[1] - mn0);
            e1[2] = ex2(e1[2] - mn1); e1[3] = ex2(e1[3] - mn1);
            rs0 += e0[0] + e0[1] + e1[0] + e1[1];
            rs1 += e0[2] + e0[3] + e1[2] + e1[3];
            pf[tp][0] = h2u(e0[0], e0[1]);
            pf[tp][1] = h2u(e0[2], e0[3]);
            pf[tp][2] = h2u(e1[0], e1[1]);
            pf[tp][3] = h2u(e1[2], e1[3]);
        }
        rs0 += __shfl_xor_sync(0xffffffffu, rs0, 1);
        rs0 += __shfl_xor_sync(0xffffffffu, rs0, 2);
        rs1 += __shfl_xor_sync(0xffffffffu, rs1, 1);
        rs1 += __shfl_xor_sync(0xffffffffu, rs1, 2);
        l0 = l0 * corr0 + rs0;
        l1 = l1 * corr1 + rs1;
#pragma unroll
        for (int nt = 0; nt < 8; nt++) {
            o[nt][0] *= corr0; o[nt][1] *= corr0;
            o[nt][2] *= corr1; o[nt][3] *= corr1;
        }

#pragma unroll
        for (int ts = 0; ts < 4; ts++) {
#pragma unroll
            for (int ep = 0; ep < 4; ep++) {
                unsigned b0, b1, b2, b3;
                ldsm4t(b0, b1, b2, b3,
                       Kc + (ts * 16 + tv_row) * KST + ep * 16 + tv_col);
                mma_f16(o[2*ep][0], o[2*ep][1], o[2*ep][2], o[2*ep][3],
                        pf[ts][0], pf[ts][1], pf[ts][2], pf[ts][3], b0, b1);
                mma_f16(o[2*ep+1][0], o[2*ep+1][1], o[2*ep+1][2], o[2*ep+1][3],
                        pf[ts][0], pf[ts][1], pf[ts][2], pf[ts][3], b2, b3);
            }
        }
    };

    if (CAUSAL) {
        for (int t = 0; t < nTiles - 2; t++) tile_body(t, false);
        tile_body(nTiles - 2, true);
        tile_body(nTiles - 1, true);
    } else {
        for (int t = 0; t < nTiles; t++) tile_body(t, false);
    }

    const float inv0 = 1.f / l0, inv1 = 1.f / l1;
    float* Oh = O + (long long)(rowBlk * 128) * DD + h * DHD;
#pragma unroll
    for (int nt = 0; nt < 8; nt++) {
        const int c = nt * 8 + 2 * tig;
        *(float2*)&Oh[(long long)(mr + g)     * DD + c] =
            make_float2(o[nt][0] * inv0, o[nt][1] * inv0);
        *(float2*)&Oh[(long long)(mr + g + 8) * DD + c] =
            make_float2(o[nt][2] * inv1, o[nt][3] * inv1);
    }
}

// ---------------- add + LayerNorm (float4) -----------------------------------
__global__ __launch_bounds__(256)
void add_ln_kernel(const float* __restrict__ a, const float* __restrict__ b,
                   const float* __restrict__ gamma, const float* __restrict__ beta,
                   float* __restrict__ out, __half* __restrict__ hout)
{
    const int row = blockIdx.x;
    const int tid = threadIdx.x;
    const float4* pa = (const float4*)(a + (long long)row * DD);
    const float4* pb = (const float4*)(b + (long long)row * DD);
    __shared__ float red[256];

    float4 v = pa[tid], w = pb[tid];
    v.x += w.x; v.y += w.y; v.z += w.z; v.w += w.w;
    red[tid] = v.x + v.y + v.z + v.w; __syncthreads();
    for (int o = 128; o; o >>= 1) { if (tid < o) red[tid] += red[tid + o]; __syncthreads(); }
    const float mu = red[0] * (1.f / DD); __syncthreads();

    float var = (v.x - mu) * (v.x - mu) + (v.y - mu) * (v.y - mu)
              + (v.z - mu) * (v.z - mu) + (v.w - mu) * (v.w - mu);
    red[tid] = var; __syncthreads();
    for (int o = 128; o; o >>= 1) { if (tid < o) red[tid] += red[tid + o]; __syncthreads(); }
    const float rs = rsqrtf(red[0] * (1.f / DD) + 1e-5f); __syncthreads();

    const float4 gm = ((const float4*)gamma)[tid];
    const float4 bt = ((const float4*)beta)[tid];
    float4 ov;
    ov.x = (v.x - mu) * rs * gm.x + bt.x;
    ov.y = (v.y - mu) * rs * gm.y + bt.y;
    ov.z = (v.z - mu) * rs * gm.z + bt.z;
    ov.w = (v.w - mu) * rs * gm.w + bt.w;
    if (out) ((float4*)(out + (long long)row * DD))[tid] = ov;
    if (hout) {
        __half2* hp = (__half2*)(hout + (long long)row * DD);
        hp[2 * tid]     = __floats2half2_rn(ov.x, ov.y);
        hp[2 * tid + 1] = __floats2half2_rn(ov.z, ov.w);
    }
}

// ---------------- orchestration ----------------------------------------------
extern "C" void kernel_launch(void* const* d_in, const int* in_sizes, int n_in,
                              void* d_out, int out_size)
{
    const float* y    = (const float*)d_in[0];
    const float* enc  = (const float*)d_in[1];
    const float* Wqs  = (const float*)d_in[2];
    const float* bqs  = (const float*)d_in[3];
    const float* Wqc  = (const float*)d_in[4];
    const float* bqc  = (const float*)d_in[5];
    const float* g1   = (const float*)d_in[6];
    const float* be1  = (const float*)d_in[7];
    const float* g2   = (const float*)d_in[8];
    const float* be2  = (const float*)d_in[9];
    const float* g3   = (const float*)d_in[10];
    const float* be3  = (const float*)d_in[11];
    const float* w1   = (const float*)d_in[12];
    const float* b1   = (const float*)d_in[13];
    const float* w2   = (const float*)d_in[14];
    const float* b2   = (const float*)d_in[15];
    float* out = (float*)d_out;

    float *tmp, *y1, *y2;
    __half *qh, *qch, *kch, *yh, *y1h, *y2h, *ench, *wqst, *wqct, *w1t, *w2t, *hidh;
    cudaGetSymbolAddress((void**)&tmp,  g_tmp);
    cudaGetSymbolAddress((void**)&y1,   g_y1);
    cudaGetSymbolAddress((void**)&y2,   g_y2);
    cudaGetSymbolAddress((void**)&qh,   g_qh);
    cudaGetSymbolAddress((void**)&qch,  g_qch);
    cudaGetSymbolAddress((void**)&kch,  g_kch);
    cudaGetSymbolAddress((void**)&yh,   g_yh);
    cudaGetSymbolAddress((void**)&y1h,  g_y1h);
    cudaGetSymbolAddress((void**)&y2h,  g_y2h);
    cudaGetSymbolAddress((void**)&ench, g_ench);
    cudaGetSymbolAddress((void**)&wqst, g_wqst);
    cudaGetSymbolAddress((void**)&wqct, g_wqct);
    cudaGetSymbolAddress((void**)&w1t,  g_w1t);
    cudaGetSymbolAddress((void**)&w2t,  g_w2t);
    cudaGetSymbolAddress((void**)&hidh, g_hidh);

    const int GS64  = 2 * (BM + 64)  * SAH * 2;   // 55296
    const int GS128 = 2 * (BM + 128) * SAH * 2;   // 73728
    const int FSMEM = (2 * 64 + 128) * KST * 2;   // 36864

    const void* fg64  = (const void*)&gemm_h<64>;
    const void* fg128 = (const void*)&gemm_h<128>;
    const void* ffc   = (const void*)&flash_h<true>;
    const void* ffn   = (const void*)&flash_h<false>;
    cudaFuncSetAttribute(fg64,  cudaFuncAttributeMaxDynamicSharedMemorySize, GS64);
    cudaFuncSetAttribute(fg128, cudaFuncAttributeMaxDynamicSharedMemorySize, GS128);
    cudaFuncSetAttribute(ffc,   cudaFuncAttributeMaxDynamicSharedMemorySize, FSMEM);
    cudaFuncSetAttribute(ffn,   cudaFuncAttributeMaxDynamicSharedMemorySize, FSMEM);

    // ---- conversions ----
    f2h2_kernel<<<592, 256>>>(y, yh, SS * DD / 4, enc, ench, SS * DD / 4);
    conv_trans_kernel<<<dim3(DHD / 32, DD / 32, 2 * HH), dim3(32, 8)>>>(
        Wqs, wqst, Wqc, wqct, DD, DHD, HH);
    conv_trans_kernel<<<dim3(HID / 32, DD / 32, 1), dim3(32, 8)>>>(
        w1, w1t, nullptr, nullptr, DD, HID, 1);
    conv_trans_kernel<<<dim3(DD / 32, HID / 32, 1), dim3(32, 8)>>>(
        w2, w2t, nullptr, nullptr, HID, DD, 1);

    // ---- self attention (q = k = v) ----
    gemm_h<128><<<dim3(DD / 128, SS / BM, 1), 256, GS128>>>(
        yh, wqst, bqs, nullptr, qh, nullptr, nullptr, 0,
        DD, DD, DD, DD, 1, 0);
    flash_h<true><<<dim3(SS / 128, HH), 256, FSMEM>>>(qh, qh, tmp);
    add_ln_kernel<<<SS, 256>>>(y, tmp, g1, be1, y1, y1h);

    // ---- cross attention ----
    gemm_h<128><<<dim3(DD / 128, SS / BM, 2), 256, GS128>>>(
        y1h, wqct, bqc, nullptr, qch, ench, kch, 1,
        DD, DD, DD, DD, 1, 0);
    flash_h<false><<<dim3(SS / 128, HH), 256, FSMEM>>>(qch, kch, tmp);
    add_ln_kernel<<<SS, 256>>>(y1, tmp, g2, be2, y2, y2h);

    // ---- FFN ----
    gemm_h<128><<<dim3(HID / 128, SS / BM, 1), 256, GS128>>>(
        y2h, w1t, b1, nullptr, hidh, nullptr, nullptr, 0,
        DD, DD, DD, HID, 0, 1);
    gemm_h<64><<<dim3(DD / 64, SS / BM, 1), 256, GS64>>>(
        hidh, w2t, b2, tmp, nullptr, nullptr, nullptr, 0,
        HID, HID, HID, DD, 0, 0);
    add_ln_kernel<<<SS, 256>>>(y2, tmp, g3, be3, out, nullptr);
}